// round 3
// baseline (speedup 1.0000x reference)
#include <cuda_runtime.h>

#define NN 65536
#define EE 524288
#define BB 1024
#define FEATN 64
#define NCLS 5
#define EN (EE + NN)
#define INF_F __int_as_float(0x7f800000)

// ---------------- scratch (device globals; no allocs allowed) ----------------
__device__ float d_u[256];
__device__ float d_v[256];
__device__ float d_vb1[256];
__device__ float d_p[4], d_q[4], d_r[4], d_t[4];
__device__ __align__(16) float d_W2e[256 * 68];
__device__ __align__(16) float4 d_S0[NN];
__device__ __align__(16) float4 d_S1[NN];
__device__ __align__(16) float d_g[NN * 64];
__device__ float d_a2s[NN];
__device__ float d_a2d[NN];
__device__ __align__(16) float d_out2[NN * 64];     // h2
__device__ __align__(16) float d_pool[BB * 64];
__device__ int d_cnt[BB];
__device__ float d_fa[64];
// piecewise-linear GEMM tables
__device__ float d_thr[8 * 64];
__device__ __align__(16) float2 d_tab[8 * 65 * 68];
// CSR (destination-sorted edges)
__device__ int d_deg[NN];
__device__ int d_offs[NN];
__device__ int d_cur[NN];
__device__ int d_csr[EE];

// ---------------- zero scratch (fresh every replay) ----------------
__global__ void zero_k() {
    int i0 = blockIdx.x * blockDim.x + threadIdx.x;
    int stride = gridDim.x * blockDim.x;
    float* s0 = (float*)d_S0;
    float* s1 = (float*)d_S1;
    for (int i = i0; i < NN * 4; i += stride) { s0[i] = 0.f; s1[i] = 0.f; }
    for (int i = i0; i < NN; i += stride) { d_deg[i] = 0; d_cur[i] = 0; }
    for (int i = i0; i < BB * 64; i += stride) d_pool[i] = 0.f;
    for (int i = i0; i < BB; i += stride) d_cnt[i] = 0;
    if (i0 < 64) d_fa[i0] = 0.f;
}

// ---------------- CSR build ----------------
__global__ void hist_k(const int* __restrict__ ei) {
    int e = blockIdx.x * 256 + threadIdx.x;
    if (e < EE) atomicAdd(&d_deg[ei[EE + e]], 1);
}

__global__ void scan_k() {
    __shared__ int sh[1024];
    int t = threadIdx.x;            // 1024 threads, 64 elems each
    int base = t * 64;
    int s = 0;
    for (int i = 0; i < 64; i++) s += d_deg[base + i];
    sh[t] = s;
    __syncthreads();
    for (int o = 1; o < 1024; o <<= 1) {
        int v = 0;
        if (t >= o) v = sh[t - o];
        __syncthreads();
        if (t >= o) sh[t] += v;
        __syncthreads();
    }
    int run = sh[t] - s;            // exclusive
    for (int i = 0; i < 64; i++) {
        int dv = d_deg[base + i];
        d_offs[base + i] = run;
        run += dv;
    }
}

__global__ void scatter_k(const int* __restrict__ ei) {
    int e = blockIdx.x * 256 + threadIdx.x;
    if (e >= EE) return;
    int s = ei[e], d = ei[EE + e];
    int pos = d_offs[d] + atomicAdd(&d_cur[d], 1);
    d_csr[pos] = s;
}

// ---------------- precompute rank-1 constants + extended W2 ----------------
__global__ void prep_k(const float* __restrict__ Win, const float* __restrict__ bin,
                       const float* __restrict__ W1, const float* __restrict__ a1s,
                       const float* __restrict__ a1d, const float* __restrict__ b1,
                       const float* __restrict__ W2, const float* __restrict__ a2sv,
                       const float* __restrict__ a2dv) {
    int j = threadIdx.x;  // 0..255
    float u = 0.f, v = 0.f;
    for (int k = 0; k < 64; k++) {
        float w1 = W1[k * 256 + j];
        u += Win[k] * w1;
        v += bin[k] * w1;
    }
    d_u[j] = u;
    d_v[j] = v;
    d_vb1[j] = v + b1[j];
    float as = 0.f, ad = 0.f;
    for (int c = 0; c < 64; c++) {
        float w2 = W2[j * 64 + c];
        d_W2e[j * 68 + c] = w2;
        as += w2 * a2sv[c];
        ad += w2 * a2dv[c];
    }
    d_W2e[j * 68 + 64] = as;
    d_W2e[j * 68 + 65] = ad;
    d_W2e[j * 68 + 66] = 0.f;
    d_W2e[j * 68 + 67] = 0.f;
    __syncthreads();
    if (j < 4) {
        float p = 0.f, q = 0.f, r = 0.f, t = 0.f;
        for (int c = 0; c < 64; c++) {
            int idx = j * 64 + c;
            p += d_u[idx] * a1s[idx];
            q += d_v[idx] * a1s[idx];
            r += d_u[idx] * a1d[idx];
            t += d_v[idx] * a1d[idx];
        }
        d_p[j] = p; d_q[j] = q; d_r[j] = r; d_t[j] = t;
    }
}

// ---------------- build sorted-threshold prefix/suffix tables ----------------
__global__ void prep2_k() {
    int hs = blockIdx.x;
    int h = hs >> 1, set = hs & 1;
    __shared__ float W2s[64 * 68];
    __shared__ float us[64], vbs[64], key[64];
    __shared__ int sidx[64];
    __shared__ unsigned char memb[64];
    __shared__ int n_s;
    int tid = threadIdx.x;  // 128
    if (tid < 64) {
        float u = d_u[h * 64 + tid], vb = d_vb1[h * 64 + tid];
        us[tid] = u; vbs[tid] = vb;
        bool m = (set == 0) ? (u > 0.f) : (u < 0.f);
        memb[tid] = m ? 1 : 0;
        key[tid] = m ? (-vb / u) : INF_F;
    }
    for (int i = tid; i < 64 * 68; i += 128)
        W2s[i] = d_W2e[h * 64 * 68 + i];
    __syncthreads();
    if (tid < 64) {
        float ki = key[tid];
        int r = 0;
        for (int j = 0; j < 64; j++) {
            float kj = key[j];
            r += (kj < ki) || (kj == ki && j < tid);
        }
        sidx[r] = tid;
    }
    if (tid == 0) {
        int n = 0;
        for (int j = 0; j < 64; j++) n += memb[j];
        n_s = n;
    }
    __syncthreads();
    int n = n_s;
    if (tid < 64) d_thr[hs * 64 + tid] = key[sidx[tid]];
    if (tid < 68) {
        int c = tid;
        if (set == 0) {
            float base = 0.f;
            for (int j = 0; j < 64; j++)
                if (us[j] == 0.f && vbs[j] > 0.f) base += vbs[j] * W2s[j * 68 + c];
            float au = 0.f, av = base;
            d_tab[(hs * 65 + 0) * 68 + c] = make_float2(au, av);
            for (int s = 0; s < 64; s++) {
                if (s < n) {
                    int k = sidx[s];
                    au += us[k] * W2s[k * 68 + c];
                    av += vbs[k] * W2s[k * 68 + c];
                }
                d_tab[(hs * 65 + s + 1) * 68 + c] = make_float2(au, av);
            }
        } else {
            for (int s = n; s <= 64; s++)
                d_tab[(hs * 65 + s) * 68 + c] = make_float2(0.f, 0.f);
            float au = 0.f, av = 0.f;
            for (int s = n - 1; s >= 0; s--) {
                int k = sidx[s];
                au += us[k] * W2s[k * 68 + c];
                av += vbs[k] * W2s[k * 68 + c];
                d_tab[(hs * 65 + s) * 68 + c] = make_float2(au, av);
            }
        }
    }
}

// ---------------- GAT-1 edge pass: accumulate S0 and S1 ----------------
__global__ void gat1_k(const int* __restrict__ ei, const float* __restrict__ x) {
    int idx = blockIdx.x * 256 + threadIdx.x;
    if (idx >= EN) return;
    int s, d;
    if (idx < EE) { s = ei[idx]; d = ei[EE + idx]; }
    else          { s = idx - EE; d = s; }
    float xs = __ldg(&x[s]);
    float xd = __ldg(&x[d]);
    float ex[4];
#pragma unroll
    for (int h = 0; h < 4; h++) {
        float e = xs * d_p[h] + d_q[h] + xd * d_r[h] + d_t[h];
        e = (e > 0.f) ? e : 0.2f * e;
        ex[h] = expf(e);
    }
    atomicAdd(&d_S0[d], make_float4(ex[0], ex[1], ex[2], ex[3]));
    atomicAdd(&d_S1[d], make_float4(ex[0] * xs, ex[1] * xs, ex[2] * xs, ex[3] * xs));
}

// ---------------- piecewise-linear "GEMM": warp per node ----------------
__global__ void g2_k() {
    __shared__ float thrS[8 * 64];
    int tid = threadIdx.x;  // 256
    for (int i = tid; i < 512; i += 256) thrS[i] = d_thr[i];
    __syncthreads();
    int lane = tid & 31, w = tid >> 5;
    int node = blockIdx.x * 8 + w;
    float4 s0 = d_S0[node], s1 = d_S1[node];
    float wh[4] = { s1.x / s0.x, s1.y / s0.y, s1.z / s0.z, s1.w / s0.w };
    float acc0 = 0.f, acc1 = 0.f, acc2 = 0.f;
#pragma unroll
    for (int hs = 0; hs < 8; hs++) {
        float wv = wh[hs >> 1];
        float t0 = thrS[hs * 64 + lane];
        float t1 = thrS[hs * 64 + 32 + lane];
        bool p0, p1;
        if ((hs & 1) == 0) { p0 = t0 < wv;  p1 = t1 < wv; }
        else               { p0 = t0 <= wv; p1 = t1 <= wv; }
        int cnt = __popc(__ballot_sync(0xffffffffu, p0)) +
                  __popc(__ballot_sync(0xffffffffu, p1));
        const float2* ptr = &d_tab[(hs * 65 + cnt) * 68];
        float2 e0 = __ldg(&ptr[lane]);
        float2 e1 = __ldg(&ptr[lane + 32]);
        acc0 += wv * e0.x + e0.y;
        acc1 += wv * e1.x + e1.y;
        if (lane < 2) {
            float2 e2 = __ldg(&ptr[64 + lane]);
            acc2 += wv * e2.x + e2.y;
        }
    }
    d_g[node * 64 + lane] = acc0;
    d_g[node * 64 + 32 + lane] = acc1;
    if (lane == 0) d_a2s[node] = acc2;
    if (lane == 1) d_a2d[node] = acc2;
}

// ---------------- GAT-2 gather (warp per dest node) + relu/bias + pooling ----------------
__global__ void gather_k(const int* __restrict__ batch, const float* __restrict__ b2) {
    int tid = threadIdx.x;          // 256
    int lane = tid & 31, w = tid >> 5;
    int node = blockIdx.x * 8 + w;
    int off = d_offs[node], deg = d_deg[node];
    float a2dd = d_a2d[node];
    // self loop
    float el = d_a2s[node] + a2dd;
    el = (el > 0.f) ? el : 0.2f * el;
    float exs = expf(el);
    float den = exs;
    float2 gv = *(const float2*)&d_g[node * 64 + lane * 2];
    float2 acc = make_float2(exs * gv.x, exs * gv.y);
    for (int base = 0; base < deg; base += 32) {
        int i = base + lane;
        int s = 0;
        float exl = 0.f;
        if (i < deg) {
            s = __ldg(&d_csr[off + i]);
            float e2 = __ldg(&d_a2s[s]) + a2dd;
            e2 = (e2 > 0.f) ? e2 : 0.2f * e2;
            exl = expf(e2);
        }
        int m = deg - base; if (m > 32) m = 32;
        for (int j = 0; j < m; j++) {
            int sj = __shfl_sync(0xffffffffu, s, j);
            float exj = __shfl_sync(0xffffffffu, exl, j);
            float2 gj = *(const float2*)&d_g[sj * 64 + lane * 2];
            acc.x += exj * gj.x;
            acc.y += exj * gj.y;
            den += exj;
        }
    }
    float inv = 1.f / den;
    float2 bb = *(const float2*)&b2[lane * 2];
    float h0 = fmaxf(acc.x * inv + bb.x, 0.f);
    float h1 = fmaxf(acc.y * inv + bb.y, 0.f);
    *(float2*)&d_out2[node * 64 + lane * 2] = make_float2(h0, h1);
    int bg = __ldg(&batch[node]);
    atomicAdd((float2*)&d_pool[bg * 64 + lane * 2], make_float2(h0, h1));
    if (lane == 0) atomicAdd(&d_cnt[bg], 1);
}

// ---------------- feature attention: per-node 64x64 matvec + sigmoid ----------------
__global__ void att_k(const float* __restrict__ faW1, const float* __restrict__ fab1,
                      const float* __restrict__ faW2, const float* __restrict__ fab2,
                      const int* __restrict__ batch) {
    __shared__ __align__(16) float W1s[64 * 64];
    __shared__ __align__(16) float b1s[64];
    __shared__ __align__(16) float w2s[64];
    __shared__ float fas[64];
    int tid = threadIdx.x;  // 128
    for (int i = tid; i < 4096; i += 128) W1s[i] = faW1[i];
    if (tid < 64) { b1s[tid] = fab1[tid]; w2s[tid] = faW2[tid]; fas[tid] = 0.f; }
    __syncthreads();
    int n = blockIdx.x * 128 + tid;
    float hrow[64];
#pragma unroll
    for (int i = 0; i < 16; i++) {
        float4 v = *(const float4*)&d_out2[n * 64 + i * 4];
        hrow[i * 4] = v.x; hrow[i * 4 + 1] = v.y;
        hrow[i * 4 + 2] = v.z; hrow[i * 4 + 3] = v.w;
    }
    float res = fab2[0];
#pragma unroll
    for (int tc = 0; tc < 4; tc++) {
        float4 acc[4];
#pragma unroll
        for (int i = 0; i < 4; i++) acc[i] = *(const float4*)&b1s[tc * 16 + i * 4];
#pragma unroll
        for (int c = 0; c < 64; c++) {
            float hc = hrow[c];
#pragma unroll
            for (int i = 0; i < 4; i++) {
                float4 wv = *(const float4*)&W1s[c * 64 + tc * 16 + i * 4];
                acc[i].x += hc * wv.x; acc[i].y += hc * wv.y;
                acc[i].z += hc * wv.z; acc[i].w += hc * wv.w;
            }
        }
#pragma unroll
        for (int i = 0; i < 4; i++) {
            float4 wv2 = *(const float4*)&w2s[tc * 16 + i * 4];
            res += fmaxf(acc[i].x, 0.f) * wv2.x + fmaxf(acc[i].y, 0.f) * wv2.y +
                   fmaxf(acc[i].z, 0.f) * wv2.z + fmaxf(acc[i].w, 0.f) * wv2.w;
        }
    }
    float att = 1.f / (1.f + expf(-res));
    int f = n - batch[n] * FEATN;
    atomicAdd(&fas[f], att);
    __syncthreads();
    if (tid < 64) atomicAdd(&d_fa[tid], fas[tid]);
}

// ---------------- classifier + final_attention ----------------
__global__ void fin_k(const float* __restrict__ clsW, const float* __restrict__ clsb,
                      float* __restrict__ out) {
    if (blockIdx.x < 4) {
        int b = blockIdx.x * 256 + threadIdx.x;
        float inv = 1.f / fmaxf((float)d_cnt[b], 1.f);
        float p[64];
#pragma unroll
        for (int i = 0; i < 16; i++) {
            float4 v = *(const float4*)&d_pool[b * 64 + i * 4];
            p[i * 4] = v.x * inv; p[i * 4 + 1] = v.y * inv;
            p[i * 4 + 2] = v.z * inv; p[i * 4 + 3] = v.w * inv;
        }
#pragma unroll
        for (int j = 0; j < NCLS; j++) {
            float o = clsb[j];
#pragma unroll
            for (int c = 0; c < 64; c++) o += p[c] * clsW[c * NCLS + j];
            out[b * NCLS + j] = o;
        }
    } else {
        int f = threadIdx.x;
        if (f < 64) out[BB * NCLS + f] = d_fa[f] * (1.f / (float)BB);
    }
}

extern "C" void kernel_launch(void* const* d_in, const int* in_sizes, int n_in,
                              void* d_out, int out_size) {
    const float* x    = (const float*)d_in[0];
    const int*   ei   = (const int*)d_in[1];
    const int*   bat  = (const int*)d_in[2];
    const float* Win  = (const float*)d_in[3];
    const float* bin  = (const float*)d_in[4];
    const float* W1   = (const float*)d_in[5];
    const float* a1s  = (const float*)d_in[6];
    const float* a1d  = (const float*)d_in[7];
    const float* b1   = (const float*)d_in[8];
    const float* W2   = (const float*)d_in[9];
    const float* a2s  = (const float*)d_in[10];
    const float* a2d  = (const float*)d_in[11];
    const float* b2   = (const float*)d_in[12];
    const float* faW1 = (const float*)d_in[13];
    const float* fab1 = (const float*)d_in[14];
    const float* faW2 = (const float*)d_in[15];
    const float* fab2 = (const float*)d_in[16];
    const float* clsW = (const float*)d_in[17];
    const float* clsb = (const float*)d_in[18];
    float* out = (float*)d_out;

    zero_k<<<512, 256>>>();
    prep_k<<<1, 256>>>(Win, bin, W1, a1s, a1d, b1, W2, a2s, a2d);
    prep2_k<<<8, 128>>>();
    hist_k<<<EE / 256, 256>>>(ei);
    scan_k<<<1, 1024>>>();
    scatter_k<<<EE / 256, 256>>>(ei);
    gat1_k<<<(EN + 255) / 256, 256>>>(ei, x);
    g2_k<<<NN / 8, 256>>>();
    gather_k<<<NN / 8, 256>>>(bat, b2);
    att_k<<<NN / 128, 128>>>(faW1, fab1, faW2, fab2, bat);
    fin_k<<<5, 256>>>(clsW, clsb, out);
}

// round 5
// speedup vs baseline: 1.7604x; 1.7604x over previous
#include <cuda_runtime.h>
#include <cuda_fp16.h>

#define NN 65536
#define EE 524288
#define BB 1024
#define FEATN 64
#define NCLS 5
#define EN (EE + NN)
#define INF_F __int_as_float(0x7f800000)

// ---------------- scratch (device globals; no allocs allowed) ----------------
__device__ float d_u[256];
__device__ float d_v[256];
__device__ float d_vb1[256];
__device__ float d_p[4], d_q[4], d_r[4], d_t[4];
__device__ __align__(16) float d_W2e[256 * 68];
__device__ __align__(16) float4 d_S0[NN];
__device__ __align__(16) float4 d_S1[NN];
__device__ __align__(16) __half2 d_gh[NN * 32];     // g rows, fp16: entry k = cols (2k, 2k+1)
__device__ float d_a2s[NN];
__device__ float d_a2d[NN];
__device__ float d_den2[NN];
__device__ __align__(16) float d_out2[NN * 64];     // gat2 numerator, then h2 in place
__device__ __align__(16) float d_pool[BB * 64];
__device__ int d_cnt[BB];
__device__ float d_fa[64];
// piecewise-linear GEMM tables (half precision)
__device__ float d_thr[8 * 64];
__device__ __align__(16) __half2 d_tab[8 * 65 * 68];

// ---------------- zero scratch (fresh every replay) ----------------
__global__ void zero_k() {
    int i0 = blockIdx.x * blockDim.x + threadIdx.x;
    int stride = gridDim.x * blockDim.x;
    for (int i = i0; i < NN * 64; i += stride) d_out2[i] = 0.f;
    float* s0 = (float*)d_S0;
    float* s1 = (float*)d_S1;
    for (int i = i0; i < NN * 4; i += stride) { s0[i] = 0.f; s1[i] = 0.f; }
    for (int i = i0; i < NN; i += stride) d_den2[i] = 0.f;
    for (int i = i0; i < BB * 64; i += stride) d_pool[i] = 0.f;
    for (int i = i0; i < BB; i += stride) d_cnt[i] = 0;
    if (i0 < 64) d_fa[i0] = 0.f;
}

// ---------------- precompute rank-1 constants + extended W2 ----------------
__global__ void prep_k(const float* __restrict__ Win, const float* __restrict__ bin,
                       const float* __restrict__ W1, const float* __restrict__ a1s,
                       const float* __restrict__ a1d, const float* __restrict__ b1,
                       const float* __restrict__ W2, const float* __restrict__ a2sv,
                       const float* __restrict__ a2dv) {
    int j = threadIdx.x;  // 0..255
    float u = 0.f, v = 0.f;
    for (int k = 0; k < 64; k++) {
        float w1 = W1[k * 256 + j];
        u += Win[k] * w1;
        v += bin[k] * w1;
    }
    d_u[j] = u;
    d_v[j] = v;
    d_vb1[j] = v + b1[j];
    float as = 0.f, ad = 0.f;
    for (int c = 0; c < 64; c++) {
        float w2 = W2[j * 64 + c];
        d_W2e[j * 68 + c] = w2;
        as += w2 * a2sv[c];
        ad += w2 * a2dv[c];
    }
    d_W2e[j * 68 + 64] = as;
    d_W2e[j * 68 + 65] = ad;
    d_W2e[j * 68 + 66] = 0.f;
    d_W2e[j * 68 + 67] = 0.f;
    __syncthreads();
    if (j < 4) {
        float p = 0.f, q = 0.f, r = 0.f, t = 0.f;
        for (int c = 0; c < 64; c++) {
            int idx = j * 64 + c;
            p += d_u[idx] * a1s[idx];
            q += d_v[idx] * a1s[idx];
            r += d_u[idx] * a1d[idx];
            t += d_v[idx] * a1d[idx];
        }
        d_p[j] = p; d_q[j] = q; d_r[j] = r; d_t[j] = t;
    }
}

// ---------------- build sorted-threshold prefix/suffix tables ----------------
__global__ void prep2_k() {
    int hs = blockIdx.x;
    int h = hs >> 1, set = hs & 1;
    __shared__ float W2s[64 * 68];
    __shared__ float us[64], vbs[64], key[64];
    __shared__ int sidx[64];
    __shared__ unsigned char memb[64];
    __shared__ int n_s;
    int tid = threadIdx.x;  // 128
    if (tid < 64) {
        float u = d_u[h * 64 + tid], vb = d_vb1[h * 64 + tid];
        us[tid] = u; vbs[tid] = vb;
        bool m = (set == 0) ? (u > 0.f) : (u < 0.f);
        memb[tid] = m ? 1 : 0;
        key[tid] = m ? (-vb / u) : INF_F;
    }
    for (int i = tid; i < 64 * 68; i += 128)
        W2s[i] = d_W2e[h * 64 * 68 + i];
    __syncthreads();
    if (tid < 64) {
        float ki = key[tid];
        int r = 0;
        for (int j = 0; j < 64; j++) {
            float kj = key[j];
            r += (kj < ki) || (kj == ki && j < tid);
        }
        sidx[r] = tid;
    }
    if (tid == 0) {
        int n = 0;
        for (int j = 0; j < 64; j++) n += memb[j];
        n_s = n;
    }
    __syncthreads();
    int n = n_s;
    if (tid < 64) d_thr[hs * 64 + tid] = key[sidx[tid]];
    if (tid < 68) {
        int c = tid;
        if (set == 0) {
            float base = 0.f;
            for (int j = 0; j < 64; j++)
                if (us[j] == 0.f && vbs[j] > 0.f) base += vbs[j] * W2s[j * 68 + c];
            float au = 0.f, av = base;
            d_tab[(hs * 65 + 0) * 68 + c] = __float22half2_rn(make_float2(au, av));
            for (int s = 0; s < 64; s++) {
                if (s < n) {
                    int k = sidx[s];
                    au += us[k] * W2s[k * 68 + c];
                    av += vbs[k] * W2s[k * 68 + c];
                }
                d_tab[(hs * 65 + s + 1) * 68 + c] = __float22half2_rn(make_float2(au, av));
            }
        } else {
            for (int s = n; s <= 64; s++)
                d_tab[(hs * 65 + s) * 68 + c] = __float22half2_rn(make_float2(0.f, 0.f));
            float au = 0.f, av = 0.f;
            for (int s = n - 1; s >= 0; s--) {
                int k = sidx[s];
                au += us[k] * W2s[k * 68 + c];
                av += vbs[k] * W2s[k * 68 + c];
                d_tab[(hs * 65 + s) * 68 + c] = __float22half2_rn(make_float2(au, av));
            }
        }
    }
}

// ---------------- GAT-1 edge pass: accumulate S0 and S1 ----------------
__global__ void gat1_k(const int* __restrict__ ei, const float* __restrict__ x) {
    int idx = blockIdx.x * 256 + threadIdx.x;
    if (idx >= EN) return;
    int s, d;
    if (idx < EE) { s = ei[idx]; d = ei[EE + idx]; }
    else          { s = idx - EE; d = s; }
    float xs = __ldg(&x[s]);
    float xd = __ldg(&x[d]);
    float ex[4];
#pragma unroll
    for (int h = 0; h < 4; h++) {
        float e = xs * d_p[h] + d_q[h] + xd * d_r[h] + d_t[h];
        e = (e > 0.f) ? e : 0.2f * e;
        ex[h] = __expf(e);
    }
    atomicAdd(&d_S0[d], make_float4(ex[0], ex[1], ex[2], ex[3]));
    atomicAdd(&d_S1[d], make_float4(ex[0] * xs, ex[1] * xs, ex[2] * xs, ex[3] * xs));
}

// ---------------- piecewise-linear "GEMM": warp per node ----------------
__global__ void g2_k() {
    __shared__ float thrS[8 * 64];
    int tid = threadIdx.x;  // 256
    for (int i = tid; i < 512; i += 256) thrS[i] = d_thr[i];
    __syncthreads();
    int lane = tid & 31, w = tid >> 5;
    int node = blockIdx.x * 8 + w;
    float4 s0 = d_S0[node], s1 = d_S1[node];
    float wh[4] = { s1.x / s0.x, s1.y / s0.y, s1.z / s0.z, s1.w / s0.w };
    float acc0 = 0.f, acc1 = 0.f, acc2 = 0.f;
#pragma unroll
    for (int hs = 0; hs < 8; hs++) {
        float wv = wh[hs >> 1];
        float t0 = thrS[hs * 64 + lane];
        float t1 = thrS[hs * 64 + 32 + lane];
        bool p0, p1;
        if ((hs & 1) == 0) { p0 = t0 < wv;  p1 = t1 < wv; }
        else               { p0 = t0 <= wv; p1 = t1 <= wv; }
        int cnt = __popc(__ballot_sync(0xffffffffu, p0)) +
                  __popc(__ballot_sync(0xffffffffu, p1));
        const __half2* ptr = &d_tab[(hs * 65 + cnt) * 68];
        uint2 tp = *(const uint2*)&ptr[2 * lane];
        float2 e0 = __half22float2(*(__half2*)&tp.x);
        float2 e1 = __half22float2(*(__half2*)&tp.y);
        acc0 += wv * e0.x + e0.y;   // col 2*lane
        acc1 += wv * e1.x + e1.y;   // col 2*lane+1
        if (lane < 2) {
            float2 e2 = __half22float2(__ldg(&ptr[64 + lane]));
            acc2 += wv * e2.x + e2.y;
        }
    }
    d_gh[node * 32 + lane] = __floats2half2_rn(acc0, acc1);
    if (lane == 0) d_a2s[node] = acc2;
    if (lane == 1) d_a2d[node] = acc2;
}

// ---------------- GAT-2 edge pass: half-warp per edge, float4 REDs ----------------
__global__ void gat2_k(const int* __restrict__ ei) {
    int gid = blockIdx.x * 256 + threadIdx.x;
    int e = gid >> 4;
    int l = gid & 15;
    if (e >= EN) return;
    int s, d;
    if (e < EE) { s = __ldg(&ei[e]); d = __ldg(&ei[EE + e]); }
    else        { s = e - EE; d = s; }
    float el = __ldg(&d_a2s[s]) + __ldg(&d_a2d[d]);
    el = (el > 0.f) ? el : 0.2f * el;
    float ex = __expf(el);
    uint2 gp = *(const uint2*)&d_gh[s * 32 + l * 2];
    float2 f0 = __half22float2(*(__half2*)&gp.x);
    float2 f1 = __half22float2(*(__half2*)&gp.y);
    atomicAdd((float4*)&d_out2[d * 64 + l * 4],
              make_float4(ex * f0.x, ex * f0.y, ex * f1.x, ex * f1.y));
    if (l == 0) atomicAdd(&d_den2[d], ex);
}

// ---------------- h2 = relu(out2/den + b2), pool per graph (float4 lanes) ----------------
__global__ void hpool_k(const int* __restrict__ batch, const float* __restrict__ b2) {
    int gid = blockIdx.x * 256 + threadIdx.x;
    int n = gid >> 4;
    int l = gid & 15;
    float inv = 1.f / d_den2[n];
    float4 o = *(float4*)&d_out2[n * 64 + l * 4];
    float4 bb = *(const float4*)&b2[l * 4];
    float4 h;
    h.x = fmaxf(o.x * inv + bb.x, 0.f);
    h.y = fmaxf(o.y * inv + bb.y, 0.f);
    h.z = fmaxf(o.z * inv + bb.z, 0.f);
    h.w = fmaxf(o.w * inv + bb.w, 0.f);
    *(float4*)&d_out2[n * 64 + l * 4] = h;
    int bg = __ldg(&batch[n]);
    atomicAdd((float4*)&d_pool[bg * 64 + l * 4], h);
    if (l == 0) atomicAdd(&d_cnt[bg], 1);
}

// ---------------- feature attention: per-node 64x64 matvec + sigmoid ----------------
__global__ void att_k(const float* __restrict__ faW1, const float* __restrict__ fab1,
                      const float* __restrict__ faW2, const float* __restrict__ fab2,
                      const int* __restrict__ batch) {
    __shared__ __align__(16) float W1s[64 * 64];
    __shared__ __align__(16) float b1s[64];
    __shared__ __align__(16) float w2s[64];
    __shared__ float fas[64];
    int tid = threadIdx.x;  // 128
    for (int i = tid; i < 4096; i += 128) W1s[i] = faW1[i];
    if (tid < 64) { b1s[tid] = fab1[tid]; w2s[tid] = faW2[tid]; fas[tid] = 0.f; }
    __syncthreads();
    int n = blockIdx.x * 128 + tid;
    float hrow[64];
#pragma unroll
    for (int i = 0; i < 16; i++) {
        float4 v = *(const float4*)&d_out2[n * 64 + i * 4];
        hrow[i * 4] = v.x; hrow[i * 4 + 1] = v.y;
        hrow[i * 4 + 2] = v.z; hrow[i * 4 + 3] = v.w;
    }
    float res = fab2[0];
#pragma unroll
    for (int tc = 0; tc < 4; tc++) {
        float4 acc[4];
#pragma unroll
        for (int i = 0; i < 4; i++) acc[i] = *(const float4*)&b1s[tc * 16 + i * 4];
#pragma unroll
        for (int c = 0; c < 64; c++) {
            float hc = hrow[c];
#pragma unroll
            for (int i = 0; i < 4; i++) {
                float4 wv = *(const float4*)&W1s[c * 64 + tc * 16 + i * 4];
                acc[i].x += hc * wv.x; acc[i].y += hc * wv.y;
                acc[i].z += hc * wv.z; acc[i].w += hc * wv.w;
            }
        }
#pragma unroll
        for (int i = 0; i < 4; i++) {
            float4 wv2 = *(const float4*)&w2s[tc * 16 + i * 4];
            res += fmaxf(acc[i].x, 0.f) * wv2.x + fmaxf(acc[i].y, 0.f) * wv2.y +
                   fmaxf(acc[i].z, 0.f) * wv2.z + fmaxf(acc[i].w, 0.f) * wv2.w;
        }
    }
    float att = 1.f / (1.f + __expf(-res));
    int f = n - batch[n] * FEATN;
    atomicAdd(&fas[f], att);
    __syncthreads();
    if (tid < 64) atomicAdd(&d_fa[tid], fas[tid]);
}

// ---------------- classifier + final_attention ----------------
__global__ void fin_k(const float* __restrict__ clsW, const float* __restrict__ clsb,
                      float* __restrict__ out) {
    if (blockIdx.x < 4) {
        int b = blockIdx.x * 256 + threadIdx.x;
        float inv = 1.f / fmaxf((float)d_cnt[b], 1.f);
        float p[64];
#pragma unroll
        for (int i = 0; i < 16; i++) {
            float4 v = *(const float4*)&d_pool[b * 64 + i * 4];
            p[i * 4] = v.x * inv; p[i * 4 + 1] = v.y * inv;
            p[i * 4 + 2] = v.z * inv; p[i * 4 + 3] = v.w * inv;
        }
#pragma unroll
        for (int j = 0; j < NCLS; j++) {
            float o = clsb[j];
#pragma unroll
            for (int c = 0; c < 64; c++) o += p[c] * clsW[c * NCLS + j];
            out[b * NCLS + j] = o;
        }
    } else {
        int f = threadIdx.x;
        if (f < 64) out[BB * NCLS + f] = d_fa[f] * (1.f / (float)BB);
    }
}

extern "C" void kernel_launch(void* const* d_in, const int* in_sizes, int n_in,
                              void* d_out, int out_size) {
    const float* x    = (const float*)d_in[0];
    const int*   ei   = (const int*)d_in[1];
    const int*   bat  = (const int*)d_in[2];
    const float* Win  = (const float*)d_in[3];
    const float* bin  = (const float*)d_in[4];
    const float* W1   = (const float*)d_in[5];
    const float* a1s  = (const float*)d_in[6];
    const float* a1d  = (const float*)d_in[7];
    const float* b1   = (const float*)d_in[8];
    const float* W2   = (const float*)d_in[9];
    const float* a2s  = (const float*)d_in[10];
    const float* a2d  = (const float*)d_in[11];
    const float* b2   = (const float*)d_in[12];
    const float* faW1 = (const float*)d_in[13];
    const float* fab1 = (const float*)d_in[14];
    const float* faW2 = (const float*)d_in[15];
    const float* fab2 = (const float*)d_in[16];
    const float* clsW = (const float*)d_in[17];
    const float* clsb = (const float*)d_in[18];
    float* out = (float*)d_out;

    zero_k<<<1024, 256>>>();
    prep_k<<<1, 256>>>(Win, bin, W1, a1s, a1d, b1, W2, a2s, a2d);
    prep2_k<<<8, 128>>>();
    gat1_k<<<(EN + 255) / 256, 256>>>(ei, x);
    g2_k<<<NN / 8, 256>>>();
    gat2_k<<<(EN * 16 + 255) / 256, 256>>>(ei);
    hpool_k<<<NN / 16, 256>>>(bat, b2);
    att_k<<<NN / 128, 128>>>(faW1, fab1, faW2, fab2, bat);
    fin_k<<<5, 256>>>(clsW, clsb, out);
}

// round 7
// speedup vs baseline: 1.9166x; 1.0887x over previous
#include <cuda_runtime.h>
#include <cuda_fp16.h>

#define NN 65536
#define EE 524288
#define BB 1024
#define FEATN 64
#define NCLS 5
#define EN (EE + NN)
#define INF_F __int_as_float(0x7f800000)

// ---------------- scratch (device globals; no allocs allowed) ----------------
__device__ float d_u[256];
__device__ float d_v[256];
__device__ float d_vb1[256];
__device__ float d_p[4], d_q[4], d_r[4], d_t[4];
__device__ __align__(16) float d_W2e[256 * 68];
__device__ __align__(16) float4 d_S0[NN];
__device__ __align__(16) float4 d_S1[NN];
__device__ __align__(16) __half2 d_gh[NN * 32];     // g rows, fp16: entry k = cols (2k, 2k+1)
__device__ float d_a2s[NN];
__device__ float d_a2d[NN];
__device__ float d_den2[NN];
__device__ __align__(16) float d_out2[NN * 64];     // gat2 numerator (init w/ self loop in g2_k)
__device__ __align__(16) float d_pool[BB * 64];
__device__ float d_fa[64];
// piecewise-linear GEMM tables (half precision)
__device__ float d_thr[8 * 64];
__device__ __align__(16) __half2 d_tab[8 * 65 * 68];
// feature-attention weights, half2-packed
__device__ __align__(16) __half2 d_faW1h[64 * 32];
__device__ __align__(8)  __half2 d_fab1h[32];
__device__ __align__(8)  __half2 d_faW2h[32];

// ---------------- zero scratch (fresh every replay) ----------------
__global__ void zero_k() {
    int i0 = blockIdx.x * blockDim.x + threadIdx.x;
    int stride = gridDim.x * blockDim.x;
    float* s0 = (float*)d_S0;
    float* s1 = (float*)d_S1;
    for (int i = i0; i < NN * 4; i += stride) { s0[i] = 0.f; s1[i] = 0.f; }
    for (int i = i0; i < BB * 64; i += stride) d_pool[i] = 0.f;
    if (i0 < 64) d_fa[i0] = 0.f;
}

// ---------------- precompute rank-1 constants + extended W2 + fp16 fa weights ----------------
__global__ void prep_k(const float* __restrict__ Win, const float* __restrict__ bin,
                       const float* __restrict__ W1, const float* __restrict__ a1s,
                       const float* __restrict__ a1d, const float* __restrict__ b1,
                       const float* __restrict__ W2, const float* __restrict__ a2sv,
                       const float* __restrict__ a2dv, const float* __restrict__ faW1,
                       const float* __restrict__ fab1, const float* __restrict__ faW2) {
    int j = threadIdx.x;  // 0..255
    float u = 0.f, v = 0.f;
    for (int k = 0; k < 64; k++) {
        float w1 = W1[k * 256 + j];
        u += Win[k] * w1;
        v += bin[k] * w1;
    }
    d_u[j] = u;
    d_v[j] = v;
    d_vb1[j] = v + b1[j];
    float as = 0.f, ad = 0.f;
    for (int c = 0; c < 64; c++) {
        float w2 = W2[j * 64 + c];
        d_W2e[j * 68 + c] = w2;
        as += w2 * a2sv[c];
        ad += w2 * a2dv[c];
    }
    d_W2e[j * 68 + 64] = as;
    d_W2e[j * 68 + 65] = ad;
    d_W2e[j * 68 + 66] = 0.f;
    d_W2e[j * 68 + 67] = 0.f;
    // pack feature-attention weights to half2
    for (int idx = j; idx < 64 * 32; idx += 256) {
        int c = idx >> 5, k = idx & 31;
        d_faW1h[idx] = __floats2half2_rn(faW1[c * 64 + 2 * k], faW1[c * 64 + 2 * k + 1]);
    }
    if (j < 32) {
        d_fab1h[j] = __floats2half2_rn(fab1[2 * j], fab1[2 * j + 1]);
        d_faW2h[j] = __floats2half2_rn(faW2[2 * j], faW2[2 * j + 1]);
    }
    __syncthreads();
    if (j < 4) {
        float p = 0.f, q = 0.f, r = 0.f, t = 0.f;
        for (int c = 0; c < 64; c++) {
            int idx = j * 64 + c;
            p += d_u[idx] * a1s[idx];
            q += d_v[idx] * a1s[idx];
            r += d_u[idx] * a1d[idx];
            t += d_v[idx] * a1d[idx];
        }
        d_p[j] = p; d_q[j] = q; d_r[j] = r; d_t[j] = t;
    }
}

// ---------------- build sorted-threshold prefix/suffix tables ----------------
__global__ void prep2_k() {
    int hs = blockIdx.x;
    int h = hs >> 1, set = hs & 1;
    __shared__ float W2s[64 * 68];
    __shared__ float us[64], vbs[64], key[64];
    __shared__ int sidx[64];
    __shared__ unsigned char memb[64];
    __shared__ int n_s;
    int tid = threadIdx.x;  // 128
    if (tid < 64) {
        float u = d_u[h * 64 + tid], vb = d_vb1[h * 64 + tid];
        us[tid] = u; vbs[tid] = vb;
        bool m = (set == 0) ? (u > 0.f) : (u < 0.f);
        memb[tid] = m ? 1 : 0;
        key[tid] = m ? (-vb / u) : INF_F;
    }
    for (int i = tid; i < 64 * 68; i += 128)
        W2s[i] = d_W2e[h * 64 * 68 + i];
    __syncthreads();
    if (tid < 64) {
        float ki = key[tid];
        int r = 0;
        for (int j = 0; j < 64; j++) {
            float kj = key[j];
            r += (kj < ki) || (kj == ki && j < tid);
        }
        sidx[r] = tid;
    }
    if (tid == 0) {
        int n = 0;
        for (int j = 0; j < 64; j++) n += memb[j];
        n_s = n;
    }
    __syncthreads();
    int n = n_s;
    if (tid < 64) d_thr[hs * 64 + tid] = key[sidx[tid]];
    if (tid < 68) {
        int c = tid;
        if (set == 0) {
            float base = 0.f;
            for (int j = 0; j < 64; j++)
                if (us[j] == 0.f && vbs[j] > 0.f) base += vbs[j] * W2s[j * 68 + c];
            float au = 0.f, av = base;
            d_tab[(hs * 65 + 0) * 68 + c] = __float22half2_rn(make_float2(au, av));
            for (int s = 0; s < 64; s++) {
                if (s < n) {
                    int k = sidx[s];
                    au += us[k] * W2s[k * 68 + c];
                    av += vbs[k] * W2s[k * 68 + c];
                }
                d_tab[(hs * 65 + s + 1) * 68 + c] = __float22half2_rn(make_float2(au, av));
            }
        } else {
            for (int s = n; s <= 64; s++)
                d_tab[(hs * 65 + s) * 68 + c] = __float22half2_rn(make_float2(0.f, 0.f));
            float au = 0.f, av = 0.f;
            for (int s = n - 1; s >= 0; s--) {
                int k = sidx[s];
                au += us[k] * W2s[k * 68 + c];
                av += vbs[k] * W2s[k * 68 + c];
                d_tab[(hs * 65 + s) * 68 + c] = __float22half2_rn(make_float2(au, av));
            }
        }
    }
}

// ---------------- GAT-1 edge pass: accumulate S0 and S1 ----------------
__global__ void gat1_k(const int* __restrict__ ei, const float* __restrict__ x) {
    int idx = blockIdx.x * 256 + threadIdx.x;
    if (idx >= EN) return;
    int s, d;
    if (idx < EE) { s = ei[idx]; d = ei[EE + idx]; }
    else          { s = idx - EE; d = s; }
    float xs = __ldg(&x[s]);
    float xd = __ldg(&x[d]);
    float ex[4];
#pragma unroll
    for (int h = 0; h < 4; h++) {
        float e = xs * d_p[h] + d_q[h] + xd * d_r[h] + d_t[h];
        e = (e > 0.f) ? e : 0.2f * e;
        ex[h] = __expf(e);
    }
    atomicAdd(&d_S0[d], make_float4(ex[0], ex[1], ex[2], ex[3]));
    atomicAdd(&d_S1[d], make_float4(ex[0] * xs, ex[1] * xs, ex[2] * xs, ex[3] * xs));
}

// ---------------- piecewise-linear "GEMM" + GAT-2 self-loop init ----------------
__global__ void g2_k() {
    __shared__ float thrS[8 * 64];
    int tid = threadIdx.x;  // 256
    for (int i = tid; i < 512; i += 256) thrS[i] = d_thr[i];
    __syncthreads();
    int lane = tid & 31, w = tid >> 5;
    int node = blockIdx.x * 8 + w;
    float4 s0 = d_S0[node], s1 = d_S1[node];
    float wh[4] = { s1.x / s0.x, s1.y / s0.y, s1.z / s0.z, s1.w / s0.w };
    float acc0 = 0.f, acc1 = 0.f, acc2 = 0.f;
#pragma unroll
    for (int hs = 0; hs < 8; hs++) {
        float wv = wh[hs >> 1];
        float t0 = thrS[hs * 64 + lane];
        float t1 = thrS[hs * 64 + 32 + lane];
        bool p0, p1;
        if ((hs & 1) == 0) { p0 = t0 < wv;  p1 = t1 < wv; }
        else               { p0 = t0 <= wv; p1 = t1 <= wv; }
        int cnt = __popc(__ballot_sync(0xffffffffu, p0)) +
                  __popc(__ballot_sync(0xffffffffu, p1));
        const __half2* ptr = &d_tab[(hs * 65 + cnt) * 68];
        uint2 tp = *(const uint2*)&ptr[2 * lane];
        float2 e0 = __half22float2(*(__half2*)&tp.x);
        float2 e1 = __half22float2(*(__half2*)&tp.y);
        acc0 += wv * e0.x + e0.y;   // col 2*lane
        acc1 += wv * e1.x + e1.y;   // col 2*lane+1
        if (lane < 2) {
            float2 e2 = __half22float2(__ldg(&ptr[64 + lane]));
            acc2 += wv * e2.x + e2.y;
        }
    }
    d_gh[node * 32 + lane] = __floats2half2_rn(acc0, acc1);
    if (lane == 0) d_a2s[node] = acc2;
    if (lane == 1) d_a2d[node] = acc2;
    // self-loop initialization of gat2 accumulators
    float a2s_n = __shfl_sync(0xffffffffu, acc2, 0);
    float a2d_n = __shfl_sync(0xffffffffu, acc2, 1);
    float el = a2s_n + a2d_n;
    el = (el > 0.f) ? el : 0.2f * el;
    float exs = __expf(el);
    *(float2*)&d_out2[node * 64 + 2 * lane] = make_float2(exs * acc0, exs * acc1);
    if (lane == 0) d_den2[node] = exs;
}

// ---------------- GAT-2 edge pass (real edges only): half-warp per edge, float4 REDs ----------------
__global__ void gat2_k(const int* __restrict__ ei) {
    int gid = blockIdx.x * 256 + threadIdx.x;
    int e = gid >> 4;
    int l = gid & 15;
    if (e >= EE) return;
    int s = __ldg(&ei[e]), d = __ldg(&ei[EE + e]);
    float el = __ldg(&d_a2s[s]) + __ldg(&d_a2d[d]);
    el = (el > 0.f) ? el : 0.2f * el;
    float ex = __expf(el);
    uint2 gp = *(const uint2*)&d_gh[s * 32 + l * 2];
    float2 f0 = __half22float2(*(__half2*)&gp.x);
    float2 f1 = __half22float2(*(__half2*)&gp.y);
    atomicAdd((float4*)&d_out2[d * 64 + l * 4],
              make_float4(ex * f0.x, ex * f0.y, ex * f1.x, ex * f1.y));
    if (l == 0) atomicAdd(&d_den2[d], ex);
}

// ---------------- fused: h2 finalize + pooling + feature attention ----------------
__global__ void att_k(const float* __restrict__ b2, const float* __restrict__ fab2) {
    __shared__ __align__(16) __half2 W1s[64 * 32];
    __shared__ __half2 b1s[32], w2s[32];
    __shared__ float b2s[64];
    __shared__ float fas[64];
    int tid = threadIdx.x;  // 128
    for (int i = tid; i < 2048; i += 128) W1s[i] = d_faW1h[i];
    if (tid < 32) { b1s[tid] = d_fab1h[tid]; w2s[tid] = d_faW2h[tid]; }
    if (tid < 64) { b2s[tid] = b2[tid]; fas[tid] = 0.f; }
    __syncthreads();
    int n = blockIdx.x * 128 + tid;
    int bg = n >> 6;                      // batch = repeat(arange(B), 64)
    float inv = 1.f / d_den2[n];
    __half2 hh[32];
#pragma unroll
    for (int i = 0; i < 16; i++) {
        float4 o = *(const float4*)&d_out2[n * 64 + i * 4];
        float4 h;
        h.x = fmaxf(o.x * inv + b2s[i * 4 + 0], 0.f);
        h.y = fmaxf(o.y * inv + b2s[i * 4 + 1], 0.f);
        h.z = fmaxf(o.z * inv + b2s[i * 4 + 2], 0.f);
        h.w = fmaxf(o.w * inv + b2s[i * 4 + 3], 0.f);
        atomicAdd((float4*)&d_pool[bg * 64 + i * 4], h);
        hh[i * 2 + 0] = __floats2half2_rn(h.x, h.y);
        hh[i * 2 + 1] = __floats2half2_rn(h.z, h.w);
    }
    __half2 acc[32];
#pragma unroll
    for (int i = 0; i < 32; i++) acc[i] = b1s[i];
#pragma unroll
    for (int ci = 0; ci < 32; ci++) {
        __half2 hc0 = __low2half2(hh[ci]);
        __half2 hc1 = __high2half2(hh[ci]);
        const __half2* wr0 = &W1s[(2 * ci) * 32];
        const __half2* wr1 = &W1s[(2 * ci + 1) * 32];
#pragma unroll
        for (int i = 0; i < 32; i++) acc[i] = __hfma2(hc0, wr0[i], acc[i]);
#pragma unroll
        for (int i = 0; i < 32; i++) acc[i] = __hfma2(hc1, wr1[i], acc[i]);
    }
    __half2 zero2 = __float2half2_rn(0.f);
    __half2 rs = zero2;
#pragma unroll
    for (int i = 0; i < 32; i++)
        rs = __hfma2(__hmax2(acc[i], zero2), w2s[i], rs);
    float res = fab2[0] + __low2float(rs) + __high2float(rs);
    float att = 1.f / (1.f + __expf(-res));
    atomicAdd(&fas[n & 63], att);
    __syncthreads();
    if (tid < 64) atomicAdd(&d_fa[tid], fas[tid]);
}

// ---------------- classifier + final_attention ----------------
__global__ void fin_k(const float* __restrict__ clsW, const float* __restrict__ clsb,
                      float* __restrict__ out) {
    if (blockIdx.x < 4) {
        int b = blockIdx.x * 256 + threadIdx.x;
        const float inv = 1.f / (float)FEATN;   // every graph has exactly 64 nodes
        float p[64];
#pragma unroll
        for (int i = 0; i < 16; i++) {
            float4 v = *(const float4*)&d_pool[b * 64 + i * 4];
            p[i * 4] = v.x * inv; p[i * 4 + 1] = v.y * inv;
            p[i * 4 + 2] = v.z * inv; p[i * 4 + 3] = v.w * inv;
        }
#pragma unroll
        for (int j = 0; j < NCLS; j++) {
            float o = clsb[j];
#pragma unroll
            for (int c = 0; c < 64; c++) o += p[c] * clsW[c * NCLS + j];
            out[b * NCLS + j] = o;
        }
    } else {
        int f = threadIdx.x;
        if (f < 64) out[BB * NCLS + f] = d_fa[f] * (1.f / (float)BB);
    }
}

extern "C" void kernel_launch(void* const* d_in, const int* in_sizes, int n_in,
                              void* d_out, int out_size) {
    const float* x    = (const float*)d_in[0];
    const int*   ei   = (const int*)d_in[1];
    const float* Win  = (const float*)d_in[3];
    const float* bin  = (const float*)d_in[4];
    const float* W1   = (const float*)d_in[5];
    const float* a1s  = (const float*)d_in[6];
    const float* a1d  = (const float*)d_in[7];
    const float* b1   = (const float*)d_in[8];
    const float* W2   = (const float*)d_in[9];
    const float* a2s  = (const float*)d_in[10];
    const float* a2d  = (const float*)d_in[11];
    const float* b2   = (const float*)d_in[12];
    const float* faW1 = (const float*)d_in[13];
    const float* fab1 = (const float*)d_in[14];
    const float* faW2 = (const float*)d_in[15];
    const float* fab2 = (const float*)d_in[16];
    const float* clsW = (const float*)d_in[17];
    const float* clsb = (const float*)d_in[18];
    float* out = (float*)d_out;

    zero_k<<<256, 256>>>();
    prep_k<<<1, 256>>>(Win, bin, W1, a1s, a1d, b1, W2, a2s, a2d, faW1, fab1, faW2);
    prep2_k<<<8, 128>>>();
    gat1_k<<<(EN + 255) / 256, 256>>>(ei, x);
    g2_k<<<NN / 8, 256>>>();
    gat2_k<<<EE * 16 / 256, 256>>>(ei);
    att_k<<<NN / 128, 128>>>(b2, fab2);
    fin_k<<<5, 256>>>(clsW, clsb, out);
}

// round 8
// speedup vs baseline: 2.1360x; 1.1145x over previous
#include <cuda_runtime.h>
#include <cuda_fp16.h>

#define NN 65536
#define EE 524288
#define BB 1024
#define FEATN 64
#define NCLS 5
#define INF_F __int_as_float(0x7f800000)

// ---------------- scratch (device globals; no allocs allowed) ----------------
__device__ float d_p[4], d_q[4], d_r[4], d_t[4];
__device__ __align__(16) float4 d_S0[NN];
__device__ __align__(16) float4 d_S1[NN];
__device__ __align__(16) __half2 d_gh[NN * 32];     // g rows, fp16: entry k = cols (2k, 2k+1)
__device__ float d_a2s[NN];
__device__ float d_a2d[NN];
__device__ float d_den2[NN];
__device__ __align__(16) float d_out2[NN * 64];     // gat2 numerator (init w/ self loop in g2_k)
__device__ __align__(16) float d_pool[BB * 64];
__device__ float d_fa[64];
// piecewise-linear GEMM tables (half precision)
__device__ float d_thr[8 * 64];
__device__ __align__(16) __half2 d_tab[8 * 65 * 68];
// feature-attention weights, half2-packed
__device__ __align__(16) __half2 d_faW1h[64 * 32];
__device__ __align__(8)  __half2 d_fab1h[32];
__device__ __align__(8)  __half2 d_faW2h[32];

// ---------------- fused init: tables + self-loop S0/S1 + zeroing + weight packing ----------------
// blocks 0..7   : build sorted-threshold prefix/suffix table for (head,set) = blockIdx
// blocks 8..63  : compute p/q/r/t locally; initialize S0/S1 with self-loop term; zero pool
// block 8 extra : store d_p..d_t, pack fa weights to half2, zero d_fa
__global__ void init_k(const float* __restrict__ x,
                       const float* __restrict__ Win, const float* __restrict__ bin,
                       const float* __restrict__ W1, const float* __restrict__ a1s,
                       const float* __restrict__ a1d, const float* __restrict__ b1,
                       const float* __restrict__ W2, const float* __restrict__ a2sv,
                       const float* __restrict__ a2dv, const float* __restrict__ faW1,
                       const float* __restrict__ fab1, const float* __restrict__ faW2) {
    int b = blockIdx.x;
    int tid = threadIdx.x;      // 256
    if (b < 8) {
        // ---- table build for hs = b ----
        int hs = b, h = hs >> 1, set = hs & 1;
        __shared__ float W2s[64 * 68];
        __shared__ float us[64], vbs[64], key[64];
        __shared__ int sidx[64];
        __shared__ unsigned char memb[64];
        __shared__ int n_s;
        if (tid < 64) {
            float u = 0.f, v = 0.f;
            for (int k = 0; k < 64; k++) {
                float w1 = W1[k * 256 + h * 64 + tid];
                u += Win[k] * w1;
                v += bin[k] * w1;
            }
            float vb = v + b1[h * 64 + tid];
            us[tid] = u; vbs[tid] = vb;
            bool m = (set == 0) ? (u > 0.f) : (u < 0.f);
            memb[tid] = m ? 1 : 0;
            key[tid] = m ? (-vb / u) : INF_F;
        }
        // W2 rows for k in [h*64, h*64+64)
        for (int i = tid; i < 64 * 64; i += 256) {
            int j = i >> 6, c = i & 63;
            W2s[j * 68 + c] = W2[(h * 64 + j) * 64 + c];
        }
        __syncthreads();
        if (tid < 64) {
            float as = 0.f, ad = 0.f;
            for (int c = 0; c < 64; c++) {
                float w2 = W2s[tid * 68 + c];
                as += w2 * a2sv[c];
                ad += w2 * a2dv[c];
            }
            W2s[tid * 68 + 64] = as;
            W2s[tid * 68 + 65] = ad;
            W2s[tid * 68 + 66] = 0.f;
            W2s[tid * 68 + 67] = 0.f;
        }
        __syncthreads();
        if (tid < 64) {
            float ki = key[tid];
            int r = 0;
            for (int j = 0; j < 64; j++) {
                float kj = key[j];
                r += (kj < ki) || (kj == ki && j < tid);
            }
            sidx[r] = tid;
        }
        if (tid == 0) {
            int n = 0;
            for (int j = 0; j < 64; j++) n += memb[j];
            n_s = n;
        }
        __syncthreads();
        int n = n_s;
        if (tid < 64) d_thr[hs * 64 + tid] = key[sidx[tid]];
        if (tid < 68) {
            int c = tid;
            if (set == 0) {
                float base = 0.f;
                for (int j = 0; j < 64; j++)
                    if (us[j] == 0.f && vbs[j] > 0.f) base += vbs[j] * W2s[j * 68 + c];
                float au = 0.f, av = base;
                d_tab[(hs * 65 + 0) * 68 + c] = __float22half2_rn(make_float2(au, av));
                for (int s = 0; s < 64; s++) {
                    if (s < n) {
                        int k = sidx[s];
                        au += us[k] * W2s[k * 68 + c];
                        av += vbs[k] * W2s[k * 68 + c];
                    }
                    d_tab[(hs * 65 + s + 1) * 68 + c] = __float22half2_rn(make_float2(au, av));
                }
            } else {
                for (int s = n; s <= 64; s++)
                    d_tab[(hs * 65 + s) * 68 + c] = __float22half2_rn(make_float2(0.f, 0.f));
                float au = 0.f, av = 0.f;
                for (int s = n - 1; s >= 0; s--) {
                    int k = sidx[s];
                    au += us[k] * W2s[k * 68 + c];
                    av += vbs[k] * W2s[k * 68 + c];
                    d_tab[(hs * 65 + s) * 68 + c] = __float22half2_rn(make_float2(au, av));
                }
            }
        }
    } else {
        // ---- compute p/q/r/t locally (redundant per block, tiny) ----
        __shared__ float sp[4], sq[4], sr[4], st[4];
        if (tid < 4) { sp[tid] = 0.f; sq[tid] = 0.f; sr[tid] = 0.f; st[tid] = 0.f; }
        __syncthreads();
        {
            float u = 0.f, v = 0.f;
            for (int k = 0; k < 64; k++) {
                float w1 = W1[k * 256 + tid];
                u += Win[k] * w1;
                v += bin[k] * w1;
            }
            float vv = v;   // note: bias b1 does NOT enter attention logits via v (a1·(v+b1))?
            // Reference: a_s = sum(h*a_src) with h = x*u + v_full where v_full = bin@W1 (b_in=0 anyway)
            // q,t use v (= bin@W1); b1 is added after (bias of gat1 output) — matches prep_k which used d_v.
            int hh = tid >> 6;
            float as_ = a1s[tid], ad_ = a1d[tid];
            atomicAdd(&sp[hh], u * as_);
            atomicAdd(&sq[hh], vv * as_);
            atomicAdd(&sr[hh], u * ad_);
            atomicAdd(&st[hh], vv * ad_);
        }
        __syncthreads();
        if (b == 8) {
            if (tid < 4) { d_p[tid] = sp[tid]; d_q[tid] = sq[tid]; d_r[tid] = sr[tid]; d_t[tid] = st[tid]; }
            // pack feature-attention weights
            for (int idx = tid; idx < 64 * 32; idx += 256) {
                int c = idx >> 5, k = idx & 31;
                d_faW1h[idx] = __floats2half2_rn(faW1[c * 64 + 2 * k], faW1[c * 64 + 2 * k + 1]);
            }
            if (tid < 32) {
                d_fab1h[tid] = __floats2half2_rn(fab1[2 * tid], fab1[2 * tid + 1]);
                d_faW2h[tid] = __floats2half2_rn(faW2[2 * tid], faW2[2 * tid + 1]);
            }
            if (tid < 64) d_fa[tid] = 0.f;
        }
        // ---- self-loop init of S0/S1 + pool zeroing, grid-stride over 56 blocks ----
        float pr[4], qt[4];
#pragma unroll
        for (int h = 0; h < 4; h++) { pr[h] = sp[h] + sr[h]; qt[h] = sq[h] + st[h]; }
        int i0 = (b - 8) * 256 + tid;
        int stride = 56 * 256;
        for (int nn = i0; nn < NN; nn += stride) {
            float xn = __ldg(&x[nn]);
            float ex[4];
#pragma unroll
            for (int h = 0; h < 4; h++) {
                float e = xn * pr[h] + qt[h];
                e = (e > 0.f) ? e : 0.2f * e;
                ex[h] = __expf(e);
            }
            d_S0[nn] = make_float4(ex[0], ex[1], ex[2], ex[3]);
            d_S1[nn] = make_float4(ex[0] * xn, ex[1] * xn, ex[2] * xn, ex[3] * xn);
        }
        for (int i = i0; i < BB * 64; i += stride) d_pool[i] = 0.f;
    }
}

// ---------------- GAT-1 edge pass (real edges only): accumulate S0 and S1 ----------------
__global__ void gat1_k(const int* __restrict__ ei, const float* __restrict__ x) {
    int idx = blockIdx.x * 256 + threadIdx.x;   // grid covers exactly EE
    int s = ei[idx], d = ei[EE + idx];
    float xs = __ldg(&x[s]);
    float xd = __ldg(&x[d]);
    float ex[4];
#pragma unroll
    for (int h = 0; h < 4; h++) {
        float e = xs * d_p[h] + d_q[h] + xd * d_r[h] + d_t[h];
        e = (e > 0.f) ? e : 0.2f * e;
        ex[h] = __expf(e);
    }
    atomicAdd(&d_S0[d], make_float4(ex[0], ex[1], ex[2], ex[3]));
    atomicAdd(&d_S1[d], make_float4(ex[0] * xs, ex[1] * xs, ex[2] * xs, ex[3] * xs));
}

// ---------------- piecewise-linear "GEMM" + GAT-2 self-loop init ----------------
__global__ void g2_k() {
    __shared__ float thrS[8 * 64];
    int tid = threadIdx.x;  // 256
    for (int i = tid; i < 512; i += 256) thrS[i] = d_thr[i];
    __syncthreads();
    int lane = tid & 31, w = tid >> 5;
    int node = blockIdx.x * 8 + w;
    float4 s0 = d_S0[node], s1 = d_S1[node];
    float wh[4] = { s1.x / s0.x, s1.y / s0.y, s1.z / s0.z, s1.w / s0.w };
    float acc0 = 0.f, acc1 = 0.f, acc2 = 0.f;
#pragma unroll
    for (int hs = 0; hs < 8; hs++) {
        float wv = wh[hs >> 1];
        float t0 = thrS[hs * 64 + lane];
        float t1 = thrS[hs * 64 + 32 + lane];
        bool p0, p1;
        if ((hs & 1) == 0) { p0 = t0 < wv;  p1 = t1 < wv; }
        else               { p0 = t0 <= wv; p1 = t1 <= wv; }
        int cnt = __popc(__ballot_sync(0xffffffffu, p0)) +
                  __popc(__ballot_sync(0xffffffffu, p1));
        const __half2* ptr = &d_tab[(hs * 65 + cnt) * 68];
        uint2 tp = *(const uint2*)&ptr[2 * lane];
        float2 e0 = __half22float2(*(__half2*)&tp.x);
        float2 e1 = __half22float2(*(__half2*)&tp.y);
        acc0 += wv * e0.x + e0.y;   // col 2*lane
        acc1 += wv * e1.x + e1.y;   // col 2*lane+1
        if (lane < 2) {
            float2 e2 = __half22float2(__ldg(&ptr[64 + lane]));
            acc2 += wv * e2.x + e2.y;
        }
    }
    d_gh[node * 32 + lane] = __floats2half2_rn(acc0, acc1);
    if (lane == 0) d_a2s[node] = acc2;
    if (lane == 1) d_a2d[node] = acc2;
    // self-loop initialization of gat2 accumulators
    float a2s_n = __shfl_sync(0xffffffffu, acc2, 0);
    float a2d_n = __shfl_sync(0xffffffffu, acc2, 1);
    float el = a2s_n + a2d_n;
    el = (el > 0.f) ? el : 0.2f * el;
    float exs = __expf(el);
    *(float2*)&d_out2[node * 64 + 2 * lane] = make_float2(exs * acc0, exs * acc1);
    if (lane == 0) d_den2[node] = exs;
}

// ---------------- GAT-2 edge pass (real edges only): half-warp per edge, float4 REDs ----------------
__global__ void gat2_k(const int* __restrict__ ei) {
    int gid = blockIdx.x * 256 + threadIdx.x;
    int e = gid >> 4;
    int l = gid & 15;
    int s = __ldg(&ei[e]), d = __ldg(&ei[EE + e]);
    float el = __ldg(&d_a2s[s]) + __ldg(&d_a2d[d]);
    el = (el > 0.f) ? el : 0.2f * el;
    float ex = __expf(el);
    uint2 gp = *(const uint2*)&d_gh[s * 32 + l * 2];
    float2 f0 = __half22float2(*(__half2*)&gp.x);
    float2 f1 = __half22float2(*(__half2*)&gp.y);
    atomicAdd((float4*)&d_out2[d * 64 + l * 4],
              make_float4(ex * f0.x, ex * f0.y, ex * f1.x, ex * f1.y));
    if (l == 0) atomicAdd(&d_den2[d], ex);
}

// ---------------- fused: h2 finalize + pooling + feature attention ----------------
__global__ void att_k(const float* __restrict__ b2, const float* __restrict__ fab2) {
    __shared__ __align__(16) __half2 W1s[64 * 32];
    __shared__ __half2 b1s[32], w2s[32];
    __shared__ float b2s[64];
    __shared__ float fas[64];
    int tid = threadIdx.x;  // 128
    for (int i = tid; i < 2048; i += 128) W1s[i] = d_faW1h[i];
    if (tid < 32) { b1s[tid] = d_fab1h[tid]; w2s[tid] = d_faW2h[tid]; }
    if (tid < 64) { b2s[tid] = b2[tid]; fas[tid] = 0.f; }
    __syncthreads();
    int n = blockIdx.x * 128 + tid;
    int bg = n >> 6;                      // batch = repeat(arange(B), 64)
    float inv = 1.f / d_den2[n];
    __half2 hh[32];
#pragma unroll
    for (int i = 0; i < 16; i++) {
        float4 o = *(const float4*)&d_out2[n * 64 + i * 4];
        float4 h;
        h.x = fmaxf(o.x * inv + b2s[i * 4 + 0], 0.f);
        h.y = fmaxf(o.y * inv + b2s[i * 4 + 1], 0.f);
        h.z = fmaxf(o.z * inv + b2s[i * 4 + 2], 0.f);
        h.w = fmaxf(o.w * inv + b2s[i * 4 + 3], 0.f);
        atomicAdd((float4*)&d_pool[bg * 64 + i * 4], h);
        hh[i * 2 + 0] = __floats2half2_rn(h.x, h.y);
        hh[i * 2 + 1] = __floats2half2_rn(h.z, h.w);
    }
    __half2 acc[32];
#pragma unroll
    for (int i = 0; i < 32; i++) acc[i] = b1s[i];
#pragma unroll
    for (int ci = 0; ci < 32; ci++) {
        __half2 hc0 = __low2half2(hh[ci]);
        __half2 hc1 = __high2half2(hh[ci]);
        const __half2* wr0 = &W1s[(2 * ci) * 32];
        const __half2* wr1 = &W1s[(2 * ci + 1) * 32];
#pragma unroll
        for (int i = 0; i < 32; i++) acc[i] = __hfma2(hc0, wr0[i], acc[i]);
#pragma unroll
        for (int i = 0; i < 32; i++) acc[i] = __hfma2(hc1, wr1[i], acc[i]);
    }
    __half2 zero2 = __float2half2_rn(0.f);
    __half2 rs = zero2;
#pragma unroll
    for (int i = 0; i < 32; i++)
        rs = __hfma2(__hmax2(acc[i], zero2), w2s[i], rs);
    float res = fab2[0] + __low2float(rs) + __high2float(rs);
    float att = 1.f / (1.f + __expf(-res));
    atomicAdd(&fas[n & 63], att);
    __syncthreads();
    if (tid < 64) atomicAdd(&d_fa[tid], fas[tid]);
}

// ---------------- classifier + final_attention ----------------
__global__ void fin_k(const float* __restrict__ clsW, const float* __restrict__ clsb,
                      float* __restrict__ out) {
    if (blockIdx.x < 4) {
        int b = blockIdx.x * 256 + threadIdx.x;
        const float inv = 1.f / (float)FEATN;   // every graph has exactly 64 nodes
        float p[64];
#pragma unroll
        for (int i = 0; i < 16; i++) {
            float4 v = *(const float4*)&d_pool[b * 64 + i * 4];
            p[i * 4] = v.x * inv; p[i * 4 + 1] = v.y * inv;
            p[i * 4 + 2] = v.z * inv; p[i * 4 + 3] = v.w * inv;
        }
#pragma unroll
        for (int j = 0; j < NCLS; j++) {
            float o = clsb[j];
#pragma unroll
            for (int c = 0; c < 64; c++) o += p[c] * clsW[c * NCLS + j];
            out[b * NCLS + j] = o;
        }
    } else {
        int f = threadIdx.x;
        if (f < 64) out[BB * NCLS + f] = d_fa[f] * (1.f / (float)BB);
    }
}

extern "C" void kernel_launch(void* const* d_in, const int* in_sizes, int n_in,
                              void* d_out, int out_size) {
    const float* x    = (const float*)d_in[0];
    const int*   ei   = (const int*)d_in[1];
    const float* Win  = (const float*)d_in[3];
    const float* bin  = (const float*)d_in[4];
    const float* W1   = (const float*)d_in[5];
    const float* a1s  = (const float*)d_in[6];
    const float* a1d  = (const float*)d_in[7];
    const float* b1   = (const float*)d_in[8];
    const float* W2   = (const float*)d_in[9];
    const float* a2s  = (const float*)d_in[10];
    const float* a2d  = (const float*)d_in[11];
    const float* b2   = (const float*)d_in[12];
    const float* faW1 = (const float*)d_in[13];
    const float* fab1 = (const float*)d_in[14];
    const float* faW2 = (const float*)d_in[15];
    const float* fab2 = (const float*)d_in[16];
    const float* clsW = (const float*)d_in[17];
    const float* clsb = (const float*)d_in[18];
    float* out = (float*)d_out;

    init_k<<<64, 256>>>(x, Win, bin, W1, a1s, a1d, b1, W2, a2s, a2d, faW1, fab1, faW2);
    gat1_k<<<EE / 256, 256>>>(ei, x);
    g2_k<<<NN / 8, 256>>>();
    gat2_k<<<EE * 16 / 256, 256>>>(ei);
    att_k<<<NN / 128, 128>>>(b2, fab2);
    fin_k<<<5, 256>>>(clsW, clsb, out);
}